// round 12
// baseline (speedup 1.0000x reference)
#include <cuda_runtime.h>
#include <cuda_bf16.h>
#include <cuda_fp16.h>
#include <cstdint>

#define FULL 0xffffffffu
#define NROWS 65536          // B*N
#define FD 256               // feature dim
#define MMEM 4096            // memory size
#define NCAND 16             // candidates kept (top-16), exact rescore picks top-8
#define TOPK 8

// -------- scratch (static __device__ — no allocations) --------
__device__ __align__(256) float         g_q[(size_t)NROWS * FD];   // fp32 q (rescore)
__device__ __align__(256) __half        g_qf[(size_t)NROWS * FD];  // f16 q (sim)
__device__ __align__(256) __half        g_kf[(size_t)MMEM * FD];   // f16 keys (sim)
__device__ __align__(256) int           g_cand[(size_t)NROWS * NCAND];
__device__ __align__(256) __nv_bfloat16 g_qry_h[(size_t)NROWS * FD];
__device__ __align__(256) __nv_bfloat16 g_qry_l[(size_t)NROWS * FD];
__device__ __align__(256) __nv_bfloat16 g_ret_h[(size_t)NROWS * FD];
__device__ __align__(256) __nv_bfloat16 g_ret_l[(size_t)NROWS * FD];
__device__ __align__(256) __nv_bfloat16 g_h_h[(size_t)NROWS * FD];
__device__ __align__(256) __nv_bfloat16 g_h_l[(size_t)NROWS * FD];
// split-bf16 transposed weights: [N=256][K] k-major, hi + lo
__device__ __align__(256) __nv_bfloat16 g_wqt_h[256 * 256], g_wqt_l[256 * 256];
__device__ __align__(256) __nv_bfloat16 g_w1t_h[256 * 512], g_w1t_l[256 * 512];
__device__ __align__(256) __nv_bfloat16 g_w2t_h[256 * 256], g_w2t_l[256 * 256];

// order-preserving float-bits -> uint map (monotone; all finite floats > 0)
__device__ __forceinline__ unsigned fordb(unsigned u) {
    return (u & 0x80000000u) ? ~u : (u | 0x80000000u);
}

__device__ __forceinline__ void cp16(unsigned dst, const void* src) {
    asm volatile("cp.async.cg.shared.global [%0], [%1], 16;"
                 :: "r"(dst), "l"(src) : "memory");
}
#define CP_COMMIT() asm volatile("cp.async.commit_group;" ::: "memory")
#define CP_WAIT0()  asm volatile("cp.async.wait_group 0;" ::: "memory")
#define CP_WAIT1()  asm volatile("cp.async.wait_group 1;" ::: "memory")

// ============================================================
// prep_misc: query -> split bf16 (hi/lo)   [blocks 0 .. 16383]
//            keys  -> f16                  [blocks 16384 .. 17407]
//            Wq    -> transposed split-bf16[blocks 17408 .. 17663]
// ============================================================
__global__ void prep_misc_kernel(const float* __restrict__ query,
                                 const float* __restrict__ keys,
                                 const float* __restrict__ Wq,
                                 __half* __restrict__ kf,
                                 __nv_bfloat16* __restrict__ qh,
                                 __nv_bfloat16* __restrict__ ql,
                                 __nv_bfloat16* __restrict__ wth,
                                 __nv_bfloat16* __restrict__ wtl) {
    int b = blockIdx.x, tid = threadIdx.x;
    if (b < 16384) {                       // query split, float4 granularity
        size_t i = (size_t)b * 256 + tid;
        float4 v = ((const float4*)query)[i];
        union { __nv_bfloat16 h[4]; uint2 u; } ph, pl;
        float f[4] = {v.x, v.y, v.z, v.w};
#pragma unroll
        for (int j = 0; j < 4; j++) {
            ph.h[j] = __float2bfloat16_rn(f[j]);
            pl.h[j] = __float2bfloat16_rn(f[j] - __bfloat162float(ph.h[j]));
        }
        ((uint2*)qh)[i] = ph.u;
        ((uint2*)ql)[i] = pl.u;
    } else if (b < 17408) {                // keys -> f16
        size_t i = (size_t)(b - 16384) * 256 + tid;
        float4 v = ((const float4*)keys)[i];
        union { __half h[4]; uint2 u; } p;
        p.h[0] = __float2half_rn(v.x); p.h[1] = __float2half_rn(v.y);
        p.h[2] = __float2half_rn(v.z); p.h[3] = __float2half_rn(v.w);
        ((uint2*)kf)[i] = p.u;
    } else {                               // Wq transpose+split  (K=256)
        int idx = (b - 17408) * 256 + tid;
        int n = idx >> 8, k = idx & 255;
        float v = Wq[(size_t)k * 256 + n];
        __nv_bfloat16 h = __float2bfloat16_rn(v);
        wth[(size_t)n * 256 + k] = h;
        wtl[(size_t)n * 256 + k] = __float2bfloat16_rn(v - __bfloat162float(h));
    }
}

// W1 (K=512, blocks 0..511) + W2 (K=256, blocks 512..767)
__global__ void prep_w12_kernel(const float* __restrict__ W1,
                                const float* __restrict__ W2,
                                __nv_bfloat16* __restrict__ w1h,
                                __nv_bfloat16* __restrict__ w1l,
                                __nv_bfloat16* __restrict__ w2h,
                                __nv_bfloat16* __restrict__ w2l) {
    int b = blockIdx.x, tid = threadIdx.x;
    if (b < 512) {
        int idx = b * 256 + tid;
        int n = idx / 512, k = idx - n * 512;
        float v = W1[(size_t)k * 256 + n];
        __nv_bfloat16 h = __float2bfloat16_rn(v);
        w1h[(size_t)n * 512 + k] = h;
        w1l[(size_t)n * 512 + k] = __float2bfloat16_rn(v - __bfloat162float(h));
    } else {
        int idx = (b - 512) * 256 + tid;
        int n = idx >> 8, k = idx & 255;
        float v = W2[(size_t)k * 256 + n];
        __nv_bfloat16 h = __float2bfloat16_rn(v);
        w2h[(size_t)n * 256 + k] = h;
        w2l[(size_t)n * 256 + k] = __float2bfloat16_rn(v - __bfloat162float(h));
    }
}

// ============================================================
// split-bf16 tensor-core GEMM (mma.sync), cp.async 2-stage pipeline.
// BM=128, BN=128, BK=64.  MODE 0: C fp32.  MODE 1: C fp32 + Chv f16.
// MODE 2: Chv bf16-hi + Cl bf16-lo.  CONCAT: A = [A0 | A1] along K.
// ============================================================
#define APAD 72
#define BG_STAGE (4 * 128 * APAD * 2)
#define BG_SMEM (2 * BG_STAGE)

template <int K, int CONCAT, int RELU, int MODE>
__global__ __launch_bounds__(256)
void bgemm2_kernel(const __nv_bfloat16* __restrict__ A0h,
                   const __nv_bfloat16* __restrict__ A0l,
                   const __nv_bfloat16* __restrict__ A1h,
                   const __nv_bfloat16* __restrict__ A1l,
                   const __nv_bfloat16* __restrict__ Bth,
                   const __nv_bfloat16* __restrict__ Btl,
                   const float* __restrict__ bias,
                   float* __restrict__ C,
                   void* __restrict__ Chv,
                   __nv_bfloat16* __restrict__ Cl) {
    extern __shared__ char smraw[];
    unsigned sbase = (unsigned)__cvta_generic_to_shared(smraw);
    int tid = threadIdx.x, lane = tid & 31, warp = tid >> 5;
    int row0 = blockIdx.x * 128, col0 = blockIdx.y * 128;
    const int NITER = K / 64;

    auto prefetch = [&](int it, int buf) {
        int kb = it * 64;
        const __nv_bfloat16 *Ah, *Al;
        if (CONCAT && kb >= 256) { Ah = A1h + (kb - 256); Al = A1l + (kb - 256); }
        else                     { Ah = A0h + kb;         Al = A0l + kb;         }
        const int astr = CONCAT ? 256 : K;
        unsigned s = sbase + buf * BG_STAGE;
#pragma unroll
        for (int t = 0; t < 4; t++) {
            int g = tid + t * 256;
            int r = g >> 3, q = (g & 7) * 8;
            unsigned off = (unsigned)(r * APAD + q) * 2;
            cp16(s + off,                      Ah + (size_t)(row0 + r) * astr + q);
            cp16(s + 128 * APAD * 2 + off,     Al + (size_t)(row0 + r) * astr + q);
            cp16(s + 2 * 128 * APAD * 2 + off, Bth + (size_t)(col0 + r) * K + kb + q);
            cp16(s + 3 * 128 * APAD * 2 + off, Btl + (size_t)(col0 + r) * K + kb + q);
        }
        CP_COMMIT();
    };

    int wm = warp >> 1, wn = warp & 1;
    int qr = lane >> 2, kc = (lane & 3) * 2;

    float acc[2][8][4];
#pragma unroll
    for (int mt = 0; mt < 2; mt++)
#pragma unroll
        for (int nt = 0; nt < 8; nt++)
#pragma unroll
            for (int x = 0; x < 4; x++) acc[mt][nt][x] = 0.f;

    prefetch(0, 0);

    for (int it = 0; it < NITER; it++) {
        if (it + 1 < NITER) { prefetch(it + 1, (it + 1) & 1); CP_WAIT1(); }
        else                { CP_WAIT0(); }
        __syncthreads();
        __nv_bfloat16* Ash = (__nv_bfloat16*)(smraw + (it & 1) * BG_STAGE);
        __nv_bfloat16* Asl = Ash + 128 * APAD;
        __nv_bfloat16* Bsh = Asl + 128 * APAD;
        __nv_bfloat16* Bsl = Bsh + 128 * APAD;

#pragma unroll
        for (int ksp = 0; ksp < 4; ksp++) {
            int k0 = ksp * 16;
            unsigned Ahf[2][4], Alf[2][4];
#pragma unroll
            for (int mt = 0; mt < 2; mt++) {
                const __nv_bfloat16* ph = Ash + (wm * 32 + mt * 16 + qr) * APAD + k0 + kc;
                const __nv_bfloat16* pl = Asl + (wm * 32 + mt * 16 + qr) * APAD + k0 + kc;
                Ahf[mt][0] = *(const unsigned*)(ph);
                Ahf[mt][1] = *(const unsigned*)(ph + 8 * APAD);
                Ahf[mt][2] = *(const unsigned*)(ph + 8);
                Ahf[mt][3] = *(const unsigned*)(ph + 8 * APAD + 8);
                Alf[mt][0] = *(const unsigned*)(pl);
                Alf[mt][1] = *(const unsigned*)(pl + 8 * APAD);
                Alf[mt][2] = *(const unsigned*)(pl + 8);
                Alf[mt][3] = *(const unsigned*)(pl + 8 * APAD + 8);
            }
#pragma unroll
            for (int nt = 0; nt < 8; nt++) {
                const __nv_bfloat16* pbh = Bsh + (wn * 64 + nt * 8 + qr) * APAD + k0 + kc;
                const __nv_bfloat16* pbl = Bsl + (wn * 64 + nt * 8 + qr) * APAD + k0 + kc;
                unsigned Bh0 = *(const unsigned*)(pbh);
                unsigned Bh1 = *(const unsigned*)(pbh + 8);
                unsigned Bl0 = *(const unsigned*)(pbl);
                unsigned Bl1 = *(const unsigned*)(pbl + 8);
#pragma unroll
                for (int mt = 0; mt < 2; mt++) {
#define MMA_BF16(Areg, B0, B1)                                              \
    asm volatile(                                                           \
        "mma.sync.aligned.m16n8k16.row.col.f32.bf16.bf16.f32 "              \
        "{%0,%1,%2,%3}, {%4,%5,%6,%7}, {%8,%9}, {%0,%1,%2,%3};\n"           \
        : "+f"(acc[mt][nt][0]), "+f"(acc[mt][nt][1]),                       \
          "+f"(acc[mt][nt][2]), "+f"(acc[mt][nt][3])                        \
        : "r"(Areg[mt][0]), "r"(Areg[mt][1]), "r"(Areg[mt][2]),             \
          "r"(Areg[mt][3]), "r"(B0), "r"(B1))
                    MMA_BF16(Ahf, Bh0, Bh1);   // hi*hi
                    MMA_BF16(Ahf, Bl0, Bl1);   // hi*lo
                    MMA_BF16(Alf, Bh0, Bh1);   // lo*hi
#undef MMA_BF16
                }
            }
        }
        __syncthreads();
    }

    // epilogue
#pragma unroll
    for (int mt = 0; mt < 2; mt++) {
        int rA = row0 + wm * 32 + mt * 16 + qr;
#pragma unroll
        for (int nt = 0; nt < 8; nt++) {
            int c = col0 + wn * 64 + nt * 8 + (lane & 3) * 2;
            float b0 = bias[c], b1 = bias[c + 1];
            float v0 = acc[mt][nt][0] + b0, v1 = acc[mt][nt][1] + b1;
            float v2 = acc[mt][nt][2] + b0, v3 = acc[mt][nt][3] + b1;
            if (RELU) {
                v0 = fmaxf(v0, 0.f); v1 = fmaxf(v1, 0.f);
                v2 = fmaxf(v2, 0.f); v3 = fmaxf(v3, 0.f);
            }
            if (MODE == 0 || MODE == 1) {
                *(float2*)(C + (size_t)rA * 256 + c)       = make_float2(v0, v1);
                *(float2*)(C + (size_t)(rA + 8) * 256 + c) = make_float2(v2, v3);
            }
            if (MODE == 1) {   // f16 copy for the sim kernel
                __half* Chf = (__half*)Chv;
                *(__half2*)(Chf + (size_t)rA * 256 + c)       = __floats2half2_rn(v0, v1);
                *(__half2*)(Chf + (size_t)(rA + 8) * 256 + c) = __floats2half2_rn(v2, v3);
            }
            if (MODE == 2) {   // split-bf16 hi/lo
                __nv_bfloat16* Chb = (__nv_bfloat16*)Chv;
                union { __nv_bfloat16 h[2]; unsigned u; } p, q;
                p.h[0] = __float2bfloat16_rn(v0);
                p.h[1] = __float2bfloat16_rn(v1);
                q.h[0] = __float2bfloat16_rn(v0 - __bfloat162float(p.h[0]));
                q.h[1] = __float2bfloat16_rn(v1 - __bfloat162float(p.h[1]));
                *(unsigned*)(Chb + (size_t)rA * 256 + c) = p.u;
                *(unsigned*)(Cl  + (size_t)rA * 256 + c) = q.u;
                p.h[0] = __float2bfloat16_rn(v2);
                p.h[1] = __float2bfloat16_rn(v3);
                q.h[0] = __float2bfloat16_rn(v2 - __bfloat162float(p.h[0]));
                q.h[1] = __float2bfloat16_rn(v3 - __bfloat162float(p.h[1]));
                *(unsigned*)(Chb + (size_t)(rA + 8) * 256 + c) = p.u;
                *(unsigned*)(Cl  + (size_t)(rA + 8) * 256 + c) = q.u;
            }
        }
    }
}

// ============================================================
// Fused sim GEMM (f16 mma.sync, f16 accum) + fragment-direct topk.
// 8 warps, warp tile 16x128 (warp owns full rows). Each lane keeps a
// private register top-16 of its own 2-row/32-col value stream; exact
// merge of 4 lanes -> top-16 at the end. Double-buffered cp.async keys.
// ============================================================
#define QPAD 264   // fp16 row pitch: conflict-free fragment LDS
#define SIM_TILE (128 * QPAD * 2)                 // bytes per [128][QPAD] f16 tile
#define SIM_SMEM (3 * SIM_TILE)                   // q + 2 key buffers = 202752

// update one lane-private top list (NCAND slots) with value u / index idx
#define TK_UPDATE(tv, ti, mn, u, idx) do {                                   \
    if ((u) > (mn)) {                                                        \
        bool _d = false;                                                     \
        _Pragma("unroll")                                                    \
        for (int _s = 0; _s < NCAND; _s++)                                   \
            if (!_d && (tv)[_s] == (mn)) { (tv)[_s] = (u); (ti)[_s] = (idx); _d = true; } \
        (mn) = (tv)[0];                                                      \
        _Pragma("unroll")                                                    \
        for (int _s = 1; _s < NCAND; _s++) (mn) = min((mn), (tv)[_s]);       \
    }                                                                        \
} while (0)

__global__ __launch_bounds__(256, 1)
void sim_topk_f16(const __half* __restrict__ qf,
                  const __half* __restrict__ kf,
                  int* __restrict__ cand) {
    extern __shared__ char smraw[];
    unsigned sbase = (unsigned)__cvta_generic_to_shared(smraw);
    __half* qs  = (__half*)smraw;                 // [128][QPAD]
    __half* ks0 = qs + 128 * QPAD;
    __half* ks1 = ks0 + 128 * QPAD;

    int tid = threadIdx.x, lane = tid & 31, warp = tid >> 5;
    int row0 = blockIdx.x * 128;
    int qr = lane >> 2, kc = (lane & 3) * 2;

    // stage q panel + key chunk 0
    {
        unsigned qdst = sbase;
#pragma unroll
        for (int t = 0; t < 16; t++) {
            int g = tid + t * 256;                // 4096 uint4
            int r = g >> 5, u = (g & 31) * 8;
            cp16(qdst + (unsigned)(r * QPAD + u) * 2, qf + (size_t)(row0 + r) * 256 + u);
            cp16(qdst + SIM_TILE + (unsigned)(r * QPAD + u) * 2, kf + (size_t)r * 256 + u);
        }
        CP_COMMIT();
    }

    unsigned tvA[NCAND], tvB[NCAND]; int tiA[NCAND], tiB[NCAND];
#pragma unroll
    for (int s = 0; s < NCAND; s++) { tvA[s] = 0u; tvB[s] = 0u; tiA[s] = 0; tiB[s] = 0; }
    unsigned mnA = 0u, mnB = 0u;

    for (int ch = 0; ch < 32; ch++) {
        CP_WAIT0();
        __syncthreads();          // buffer(ch) ready; prior compute done before restage
        if (ch + 1 < 32) {        // stage next chunk into the other buffer
            unsigned dst = sbase + SIM_TILE + ((ch + 1) & 1) * SIM_TILE;
            const __half* src = kf + (size_t)((ch + 1) * 128) * 256;
#pragma unroll
            for (int t = 0; t < 16; t++) {
                int g = tid + t * 256;
                int r = g >> 5, u = (g & 31) * 8;
                cp16(dst + (unsigned)(r * QPAD + u) * 2, src + (size_t)r * 256 + u);
            }
            CP_COMMIT();
        }

        const __half* kb = (ch & 1) ? ks1 : ks0;
        unsigned acc[16][2];
#pragma unroll
        for (int nt = 0; nt < 16; nt++) { acc[nt][0] = 0u; acc[nt][1] = 0u; }

#pragma unroll
        for (int ksp = 0; ksp < 16; ksp++) {
            int k0 = ksp * 16;
            const __half* pa = qs + (warp * 16 + qr) * QPAD + k0 + kc;
            unsigned a0 = *(const unsigned*)(pa);
            unsigned a1 = *(const unsigned*)(pa + 8 * QPAD);
            unsigned a2 = *(const unsigned*)(pa + 8);
            unsigned a3 = *(const unsigned*)(pa + 8 * QPAD + 8);
#pragma unroll
            for (int nt = 0; nt < 16; nt++) {
                const __half* pb = kb + (nt * 8 + qr) * QPAD + k0 + kc;
                unsigned B0 = *(const unsigned*)(pb);
                unsigned B1 = *(const unsigned*)(pb + 8);
                asm volatile(
                    "mma.sync.aligned.m16n8k16.row.col.f16.f16.f16.f16 "
                    "{%0,%1}, {%2,%3,%4,%5}, {%6,%7}, {%0,%1};\n"
                    : "+r"(acc[nt][0]), "+r"(acc[nt][1])
                    : "r"(a0), "r"(a1), "r"(a2), "r"(a3), "r"(B0), "r"(B1));
            }
        }

        // fragment-direct topk update (register-only, no cross-lane ops)
#pragma unroll
        for (int nt = 0; nt < 16; nt++) {
            int cb = ch * 128 + nt * 8 + (lane & 3) * 2;
            float2 f0 = __half22float2(*(__half2*)&acc[nt][0]);   // row warp*16+qr
            float2 f1 = __half22float2(*(__half2*)&acc[nt][1]);   // row +8
            unsigned u;
            u = fordb(__float_as_uint(f0.x)); TK_UPDATE(tvA, tiA, mnA, u, cb);
            u = fordb(__float_as_uint(f0.y)); TK_UPDATE(tvA, tiA, mnA, u, cb + 1);
            u = fordb(__float_as_uint(f1.x)); TK_UPDATE(tvB, tiB, mnB, u, cb);
            u = fordb(__float_as_uint(f1.y)); TK_UPDATE(tvB, tiB, mnB, u, cb + 1);
        }
    }
    __syncthreads();

    // ---- exact merge: 4 lanes x top-16 -> top-16 of 64, per row ----
    unsigned* mv = (unsigned*)ks0;                // [128][64]
    int*      mi = (int*)(mv + 128 * 64);         // [128][64]
    {
        int rA = warp * 16 + qr, rB = rA + 8, sb = (lane & 3) * 16;
#pragma unroll
        for (int s = 0; s < NCAND; s++) {
            mv[rA * 64 + sb + s] = tvA[s];  mi[rA * 64 + sb + s] = tiA[s];
            mv[rB * 64 + sb + s] = tvB[s];  mi[rB * 64 + sb + s] = tiB[s];
        }
    }
    __syncthreads();
    if (tid < 128) {
        int r = tid;
#pragma unroll 1
        for (int t = 0; t < NCAND; t++) {
            unsigned best = 0; int bj = 0;
#pragma unroll 1
            for (int j = 0; j < 64; j++) {
                unsigned v = mv[r * 64 + j];
                if (v > best) { best = v; bj = j; }
            }
            mv[r * 64 + bj] = 0;
            cand[(size_t)(row0 + r) * NCAND + t] = mi[r * 64 + bj];
        }
    }
}

// ============================================================
// Exact rescore: fp32 dots for 16 candidates, exact top-8,
// softmax + weighted gather of memory_values. 1 warp per query.
// Emits retrieved as split-bf16 hi/lo.
// ============================================================
__global__ __launch_bounds__(256)
void rescore_kernel(const float* __restrict__ q, const float* __restrict__ keys,
                    const float* __restrict__ values, const int* __restrict__ cand,
                    __nv_bfloat16* __restrict__ reth, __nv_bfloat16* __restrict__ retl) {
    int lane = threadIdx.x & 31, warp = threadIdx.x >> 5;
    int g = blockIdx.x * 8 + warp;

    float qv[8];
#pragma unroll
    for (int k = 0; k < 8; k++) qv[k] = q[(size_t)g * 256 + k * 32 + lane];

    int myc = cand[(size_t)g * NCAND + (lane & 15)];
    float s[NCAND]; int kid[NCAND];
#pragma unroll
    for (int c = 0; c < NCAND; c++) {
        int ki = __shfl_sync(FULL, myc, c);
        kid[c] = ki;
        const float* kr = keys + (size_t)ki * 256;
        float d = 0.f;
#pragma unroll
        for (int k = 0; k < 8; k++) d = fmaf(qv[k], kr[k * 32 + lane], d);
#pragma unroll
        for (int o = 16; o; o >>= 1) d += __shfl_xor_sync(FULL, d, o);
        s[c] = d;
    }

    bool sel[NCAND];
    float mx = -1e30f;
#pragma unroll
    for (int c = 0; c < NCAND; c++) {
        int rk = 0;
#pragma unroll
        for (int j = 0; j < NCAND; j++)
            rk += (s[j] > s[c]) || (s[j] == s[c] && j < c);
        sel[c] = (rk < TOPK);
        if (sel[c]) mx = fmaxf(mx, s[c]);
    }
    float den = 0.f, w[NCAND];
#pragma unroll
    for (int c = 0; c < NCAND; c++) {
        w[c] = sel[c] ? __expf(s[c] - mx) : 0.f;
        den += w[c];
    }
    float inv = 1.f / den;

    float accf[8];
#pragma unroll
    for (int k = 0; k < 8; k++) accf[k] = 0.f;
#pragma unroll
    for (int c = 0; c < NCAND; c++) {
        if (sel[c]) {
            const float* vr = values + (size_t)kid[c] * 256;
            float wc = w[c] * inv;
#pragma unroll
            for (int k = 0; k < 8; k++) accf[k] = fmaf(wc, vr[k * 32 + lane], accf[k]);
        }
    }
#pragma unroll
    for (int k = 0; k < 8; k++) {
        float v = accf[k];
        __nv_bfloat16 hi = __float2bfloat16_rn(v);
        reth[(size_t)g * 256 + k * 32 + lane] = hi;
        retl[(size_t)g * 256 + k * 32 + lane] =
            __float2bfloat16_rn(v - __bfloat162float(hi));
    }
}

// ============================================================
// launch   (ncu -s 5 profiles OUR 0-based launch index 3 -> sim)
// ============================================================
extern "C" void kernel_launch(void* const* d_in, const int* in_sizes, int n_in,
                              void* d_out, int out_size) {
    const float* query = (const float*)d_in[0];
    const float* mkeys = (const float*)d_in[1];
    const float* mvals = (const float*)d_in[2];
    const float* Wq    = (const float*)d_in[3];
    const float* bq    = (const float*)d_in[4];
    const float* W1    = (const float*)d_in[5];
    const float* b1    = (const float*)d_in[6];
    const float* W2    = (const float*)d_in[7];
    const float* b2    = (const float*)d_in[8];
    float* out = (float*)d_out;
    (void)in_sizes; (void)n_in; (void)out_size;

    float* qf;   cudaGetSymbolAddress((void**)&qf, g_q);
    __half* qhf; cudaGetSymbolAddress((void**)&qhf, g_qf);
    __half* khf; cudaGetSymbolAddress((void**)&khf, g_kf);
    int* candp;  cudaGetSymbolAddress((void**)&candp, g_cand);
    __nv_bfloat16 *qryh, *qryl, *reth, *retl, *hh, *hl;
    cudaGetSymbolAddress((void**)&qryh, g_qry_h);
    cudaGetSymbolAddress((void**)&qryl, g_qry_l);
    cudaGetSymbolAddress((void**)&reth, g_ret_h);
    cudaGetSymbolAddress((void**)&retl, g_ret_l);
    cudaGetSymbolAddress((void**)&hh,   g_h_h);
    cudaGetSymbolAddress((void**)&hl,   g_h_l);
    __nv_bfloat16 *wqh, *wql, *w1h, *w1l, *w2h, *w2l;
    cudaGetSymbolAddress((void**)&wqh, g_wqt_h);
    cudaGetSymbolAddress((void**)&wql, g_wqt_l);
    cudaGetSymbolAddress((void**)&w1h, g_w1t_h);
    cudaGetSymbolAddress((void**)&w1l, g_w1t_l);
    cudaGetSymbolAddress((void**)&w2h, g_w2t_h);
    cudaGetSymbolAddress((void**)&w2l, g_w2t_l);

    // 0: query split + keys->f16 + Wq prep
    prep_misc_kernel<<<17664, 256>>>(query, mkeys, Wq, khf, qryh, qryl, wqh, wql);

    // 1: q = query @ Wq + bq   (fp32 out + f16 out)
    cudaFuncSetAttribute(bgemm2_kernel<256, 0, 0, 1>,
                         cudaFuncAttributeMaxDynamicSharedMemorySize, BG_SMEM);
    bgemm2_kernel<256, 0, 0, 1><<<dim3(NROWS / 128, 2), 256, BG_SMEM>>>(
        qryh, qryl, nullptr, nullptr, wqh, wql, bq, qf, qhf, nullptr);

    // 2: W1/W2 prep (needed only by launches 5/6)
    prep_w12_kernel<<<768, 256>>>(W1, W2, w1h, w1l, w2h, w2l);

    // 3: fused sim + top-16 candidates  <-- profiled slot
    cudaFuncSetAttribute(sim_topk_f16,
                         cudaFuncAttributeMaxDynamicSharedMemorySize, SIM_SMEM);
    sim_topk_f16<<<NROWS / 128, 256, SIM_SMEM>>>(qhf, khf, candp);

    // 4: exact rescore + softmax + gather (-> split-bf16 retrieved)
    rescore_kernel<<<NROWS / 8, 256>>>(qf, mkeys, mvals, candp, reth, retl);

    // 5: h = relu(concat(query, retrieved) @ W1 + b1)  (-> split-bf16 h)
    cudaFuncSetAttribute(bgemm2_kernel<512, 1, 1, 2>,
                         cudaFuncAttributeMaxDynamicSharedMemorySize, BG_SMEM);
    bgemm2_kernel<512, 1, 1, 2><<<dim3(NROWS / 128, 2), 256, BG_SMEM>>>(
        qryh, qryl, reth, retl, w1h, w1l, b1, nullptr, hh, hl);

    // 6: out = h @ W2 + b2  (fp32)
    cudaFuncSetAttribute(bgemm2_kernel<256, 0, 0, 0>,
                         cudaFuncAttributeMaxDynamicSharedMemorySize, BG_SMEM);
    bgemm2_kernel<256, 0, 0, 0><<<dim3(NROWS / 128, 2), 256, BG_SMEM>>>(
        hh, hl, nullptr, nullptr, w2h, w2l, b2, out, nullptr, nullptr);
}

// round 13
// speedup vs baseline: 1.0019x; 1.0019x over previous
#include <cuda_runtime.h>
#include <cuda_bf16.h>
#include <cstdint>

#define FULL 0xffffffffu
#define NROWS 65536          // B*N
#define FD 256               // feature dim
#define MMEM 4096            // memory size
#define NCAND 16             // candidates kept (top-16), exact rescore picks top-8
#define TOPK 8

// -------- scratch (static __device__ — no allocations) --------
__device__ __align__(256) float         g_q[(size_t)NROWS * FD];   // fp32 q (rescore)
__device__ __align__(256) __nv_bfloat16 g_qb[(size_t)NROWS * FD];  // bf16 hi(q) for sim
__device__ __align__(256) __nv_bfloat16 g_kb[(size_t)MMEM * FD];   // bf16 keys (sim)
__device__ __align__(256) int           g_cand[(size_t)NROWS * NCAND];
__device__ __align__(256) __nv_bfloat16 g_qry_h[(size_t)NROWS * FD];
__device__ __align__(256) __nv_bfloat16 g_qry_l[(size_t)NROWS * FD];
__device__ __align__(256) __nv_bfloat16 g_ret_h[(size_t)NROWS * FD];
__device__ __align__(256) __nv_bfloat16 g_ret_l[(size_t)NROWS * FD];
__device__ __align__(256) __nv_bfloat16 g_h_h[(size_t)NROWS * FD];
__device__ __align__(256) __nv_bfloat16 g_h_l[(size_t)NROWS * FD];
// split-bf16 transposed weights: [N=256][K] k-major, hi + lo
__device__ __align__(256) __nv_bfloat16 g_wqt_h[256 * 256], g_wqt_l[256 * 256];
__device__ __align__(256) __nv_bfloat16 g_w1t_h[256 * 512], g_w1t_l[256 * 512];
__device__ __align__(256) __nv_bfloat16 g_w2t_h[256 * 256], g_w2t_l[256 * 256];

// order-preserving float-bits -> uint map (monotone; all finite floats > 0)
__device__ __forceinline__ unsigned fordb(unsigned u) {
    return (u & 0x80000000u) ? ~u : (u | 0x80000000u);
}

__device__ __forceinline__ void cp16(unsigned dst, const void* src) {
    asm volatile("cp.async.cg.shared.global [%0], [%1], 16;"
                 :: "r"(dst), "l"(src) : "memory");
}
#define CP_COMMIT() asm volatile("cp.async.commit_group;" ::: "memory")
#define CP_WAIT0()  asm volatile("cp.async.wait_group 0;" ::: "memory")
#define CP_WAIT1()  asm volatile("cp.async.wait_group 1;" ::: "memory")

// ============================================================
// launch 0: keys -> bf16 [blocks 0..1023] ; Wq transpose+split [1024..1279]
// ============================================================
__global__ void prep_kw_kernel(const float* __restrict__ keys,
                               const float* __restrict__ Wq,
                               __nv_bfloat16* __restrict__ kb,
                               __nv_bfloat16* __restrict__ wth,
                               __nv_bfloat16* __restrict__ wtl) {
    int b = blockIdx.x, tid = threadIdx.x;
    if (b < 1024) {                        // keys -> bf16, float4 granularity
        size_t i = (size_t)b * 256 + tid;
        float4 v = ((const float4*)keys)[i];
        union { __nv_bfloat16 h[4]; uint2 u; } p;
        p.h[0] = __float2bfloat16_rn(v.x);
        p.h[1] = __float2bfloat16_rn(v.y);
        p.h[2] = __float2bfloat16_rn(v.z);
        p.h[3] = __float2bfloat16_rn(v.w);
        ((uint2*)kb)[i] = p.u;
    } else {                               // Wq transpose + split (K=256)
        int idx = (b - 1024) * 256 + tid;
        int n = idx >> 8, k = idx & 255;
        float v = Wq[(size_t)k * 256 + n];
        __nv_bfloat16 h = __float2bfloat16_rn(v);
        wth[(size_t)n * 256 + k] = h;
        wtl[(size_t)n * 256 + k] = __float2bfloat16_rn(v - __bfloat162float(h));
    }
}

// ============================================================
// launch 1: query fp32 -> split bf16 hi/lo
// ============================================================
__global__ void split_f32_kernel(const float* __restrict__ x,
                                 __nv_bfloat16* __restrict__ xh,
                                 __nv_bfloat16* __restrict__ xl) {
    size_t i = (size_t)blockIdx.x * blockDim.x + threadIdx.x;
    float4 v = ((const float4*)x)[i];
    union { __nv_bfloat16 h[4]; uint2 u; } ph, pl;
    float f[4] = {v.x, v.y, v.z, v.w};
#pragma unroll
    for (int j = 0; j < 4; j++) {
        ph.h[j] = __float2bfloat16_rn(f[j]);
        pl.h[j] = __float2bfloat16_rn(f[j] - __bfloat162float(ph.h[j]));
    }
    ((uint2*)xh)[i] = ph.u;
    ((uint2*)xl)[i] = pl.u;
}

// W1 (K=512, blocks 0..511) + W2 (K=256, blocks 512..767)
__global__ void prep_w12_kernel(const float* __restrict__ W1,
                                const float* __restrict__ W2,
                                __nv_bfloat16* __restrict__ w1h,
                                __nv_bfloat16* __restrict__ w1l,
                                __nv_bfloat16* __restrict__ w2h,
                                __nv_bfloat16* __restrict__ w2l) {
    int b = blockIdx.x, tid = threadIdx.x;
    if (b < 512) {
        int idx = b * 256 + tid;
        int n = idx / 512, k = idx - n * 512;
        float v = W1[(size_t)k * 256 + n];
        __nv_bfloat16 h = __float2bfloat16_rn(v);
        w1h[(size_t)n * 512 + k] = h;
        w1l[(size_t)n * 512 + k] = __float2bfloat16_rn(v - __bfloat162float(h));
    } else {
        int idx = (b - 512) * 256 + tid;
        int n = idx >> 8, k = idx & 255;
        float v = W2[(size_t)k * 256 + n];
        __nv_bfloat16 h = __float2bfloat16_rn(v);
        w2h[(size_t)n * 256 + k] = h;
        w2l[(size_t)n * 256 + k] = __float2bfloat16_rn(v - __bfloat162float(h));
    }
}

// ============================================================
// split-bf16 tensor-core GEMM (mma.sync bf16/f32), cp.async 2-stage.
// BM=128, BN=128, BK=64.  MODE 0: C fp32.  MODE 1: C fp32 + Ch bf16-hi.
// MODE 2: Ch bf16-hi + Cl bf16-lo.  CONCAT: A = [A0 | A1] along K.
// (byte-identical math to the 3621us-proven version)
// ============================================================
#define APAD 72
#define BG_STAGE (4 * 128 * APAD * 2)
#define BG_SMEM (2 * BG_STAGE)

template <int K, int CONCAT, int RELU, int MODE>
__global__ __launch_bounds__(256)
void bgemm2_kernel(const __nv_bfloat16* __restrict__ A0h,
                   const __nv_bfloat16* __restrict__ A0l,
                   const __nv_bfloat16* __restrict__ A1h,
                   const __nv_bfloat16* __restrict__ A1l,
                   const __nv_bfloat16* __restrict__ Bth,
                   const __nv_bfloat16* __restrict__ Btl,
                   const float* __restrict__ bias,
                   float* __restrict__ C,
                   __nv_bfloat16* __restrict__ Ch,
                   __nv_bfloat16* __restrict__ Cl) {
    extern __shared__ char smraw[];
    unsigned sbase = (unsigned)__cvta_generic_to_shared(smraw);
    int tid = threadIdx.x, lane = tid & 31, warp = tid >> 5;
    int row0 = blockIdx.x * 128, col0 = blockIdx.y * 128;
    const int NITER = K / 64;

    auto prefetch = [&](int it, int buf) {
        int kb = it * 64;
        const __nv_bfloat16 *Ah, *Al;
        if (CONCAT && kb >= 256) { Ah = A1h + (kb - 256); Al = A1l + (kb - 256); }
        else                     { Ah = A0h + kb;         Al = A0l + kb;         }
        const int astr = CONCAT ? 256 : K;
        unsigned s = sbase + buf * BG_STAGE;
#pragma unroll
        for (int t = 0; t < 4; t++) {
            int g = tid + t * 256;
            int r = g >> 3, q = (g & 7) * 8;
            unsigned off = (unsigned)(r * APAD + q) * 2;
            cp16(s + off,                      Ah + (size_t)(row0 + r) * astr + q);
            cp16(s + 128 * APAD * 2 + off,     Al + (size_t)(row0 + r) * astr + q);
            cp16(s + 2 * 128 * APAD * 2 + off, Bth + (size_t)(col0 + r) * K + kb + q);
            cp16(s + 3 * 128 * APAD * 2 + off, Btl + (size_t)(col0 + r) * K + kb + q);
        }
        CP_COMMIT();
    };

    int wm = warp >> 1, wn = warp & 1;
    int qr = lane >> 2, kc = (lane & 3) * 2;

    float acc[2][8][4];
#pragma unroll
    for (int mt = 0; mt < 2; mt++)
#pragma unroll
        for (int nt = 0; nt < 8; nt++)
#pragma unroll
            for (int x = 0; x < 4; x++) acc[mt][nt][x] = 0.f;

    prefetch(0, 0);

    for (int it = 0; it < NITER; it++) {
        if (it + 1 < NITER) { prefetch(it + 1, (it + 1) & 1); CP_WAIT1(); }
        else                { CP_WAIT0(); }
        __syncthreads();
        __nv_bfloat16* Ash = (__nv_bfloat16*)(smraw + (it & 1) * BG_STAGE);
        __nv_bfloat16* Asl = Ash + 128 * APAD;
        __nv_bfloat16* Bsh = Asl + 128 * APAD;
        __nv_bfloat16* Bsl = Bsh + 128 * APAD;

#pragma unroll
        for (int ksp = 0; ksp < 4; ksp++) {
            int k0 = ksp * 16;
            unsigned Ahf[2][4], Alf[2][4];
#pragma unroll
            for (int mt = 0; mt < 2; mt++) {
                const __nv_bfloat16* ph = Ash + (wm * 32 + mt * 16 + qr) * APAD + k0 + kc;
                const __nv_bfloat16* pl = Asl + (wm * 32 + mt * 16 + qr) * APAD + k0 + kc;
                Ahf[mt][0] = *(const unsigned*)(ph);
                Ahf[mt][1] = *(const unsigned*)(ph + 8 * APAD);
                Ahf[mt][2] = *(const unsigned*)(ph + 8);
                Ahf[mt][3] = *(const unsigned*)(ph + 8 * APAD + 8);
                Alf[mt][0] = *(const unsigned*)(pl);
                Alf[mt][1] = *(const unsigned*)(pl + 8 * APAD);
                Alf[mt][2] = *(const unsigned*)(pl + 8);
                Alf[mt][3] = *(const unsigned*)(pl + 8 * APAD + 8);
            }
#pragma unroll
            for (int nt = 0; nt < 8; nt++) {
                const __nv_bfloat16* pbh = Bsh + (wn * 64 + nt * 8 + qr) * APAD + k0 + kc;
                const __nv_bfloat16* pbl = Bsl + (wn * 64 + nt * 8 + qr) * APAD + k0 + kc;
                unsigned Bh0 = *(const unsigned*)(pbh);
                unsigned Bh1 = *(const unsigned*)(pbh + 8);
                unsigned Bl0 = *(const unsigned*)(pbl);
                unsigned Bl1 = *(const unsigned*)(pbl + 8);
#pragma unroll
                for (int mt = 0; mt < 2; mt++) {
#define MMA_BF16(Areg, B0, B1)                                              \
    asm volatile(                                                           \
        "mma.sync.aligned.m16n8k16.row.col.f32.bf16.bf16.f32 "              \
        "{%0,%1,%2,%3}, {%4,%5,%6,%7}, {%8,%9}, {%0,%1,%2,%3};\n"           \
        : "+f"(acc[mt][nt][0]), "+f"(acc[mt][nt][1]),                       \
          "+f"(acc[mt][nt][2]), "+f"(acc[mt][nt][3])                        \
        : "r"(Areg[mt][0]), "r"(Areg[mt][1]), "r"(Areg[mt][2]),             \
          "r"(Areg[mt][3]), "r"(B0), "r"(B1))
                    MMA_BF16(Ahf, Bh0, Bh1);   // hi*hi
                    MMA_BF16(Ahf, Bl0, Bl1);   // hi*lo
                    MMA_BF16(Alf, Bh0, Bh1);   // lo*hi
#undef MMA_BF16
                }
            }
        }
        __syncthreads();
    }

    // epilogue
#pragma unroll
    for (int mt = 0; mt < 2; mt++) {
        int rA = row0 + wm * 32 + mt * 16 + qr;
#pragma unroll
        for (int nt = 0; nt < 8; nt++) {
            int c = col0 + wn * 64 + nt * 8 + (lane & 3) * 2;
            float b0 = bias[c], b1 = bias[c + 1];
            float v0 = acc[mt][nt][0] + b0, v1 = acc[mt][nt][1] + b1;
            float v2 = acc[mt][nt][2] + b0, v3 = acc[mt][nt][3] + b1;
            if (RELU) {
                v0 = fmaxf(v0, 0.f); v1 = fmaxf(v1, 0.f);
                v2 = fmaxf(v2, 0.f); v3 = fmaxf(v3, 0.f);
            }
            if (MODE == 0 || MODE == 1) {
                *(float2*)(C + (size_t)rA * 256 + c)       = make_float2(v0, v1);
                *(float2*)(C + (size_t)(rA + 8) * 256 + c) = make_float2(v2, v3);
            }
            if (MODE == 1) {   // bf16-hi copy for the sim kernel
                union { __nv_bfloat16 h[2]; unsigned u; } p;
                p.h[0] = __float2bfloat16_rn(v0); p.h[1] = __float2bfloat16_rn(v1);
                *(unsigned*)(Ch + (size_t)rA * 256 + c) = p.u;
                p.h[0] = __float2bfloat16_rn(v2); p.h[1] = __float2bfloat16_rn(v3);
                *(unsigned*)(Ch + (size_t)(rA + 8) * 256 + c) = p.u;
            }
            if (MODE == 2) {   // split-bf16 hi/lo
                union { __nv_bfloat16 h[2]; unsigned u; } p, q;
                p.h[0] = __float2bfloat16_rn(v0);
                p.h[1] = __float2bfloat16_rn(v1);
                q.h[0] = __float2bfloat16_rn(v0 - __bfloat162float(p.h[0]));
                q.h[1] = __float2bfloat16_rn(v1 - __bfloat162float(p.h[1]));
                *(unsigned*)(Ch + (size_t)rA * 256 + c) = p.u;
                *(unsigned*)(Cl + (size_t)rA * 256 + c) = q.u;
                p.h[0] = __float2bfloat16_rn(v2);
                p.h[1] = __float2bfloat16_rn(v3);
                q.h[0] = __float2bfloat16_rn(v2 - __bfloat162float(p.h[0]));
                q.h[1] = __float2bfloat16_rn(v3 - __bfloat162float(p.h[1]));
                *(unsigned*)(Ch + (size_t)(rA + 8) * 256 + c) = p.u;
                *(unsigned*)(Cl + (size_t)(rA + 8) * 256 + c) = q.u;
            }
        }
    }
}

// ============================================================
// Fused sim GEMM (bf16 mma.sync, f32 accum — PROVEN flavor) +
// fragment-direct register top-16. 8 warps, warp tile 16x128
// (warp owns full rows qr, qr+8 of its 16-row band). Each lane keeps
// two private top-16 lists (rows qr / qr+8, its own 32-col subset);
// exact 4-lane merge per row at the end. Double-buffered cp.async keys.
// ============================================================
#define QPAD 264   // bf16 row pitch: conflict-free fragment LDS
#define SIM_TILE (128 * QPAD * 2)                 // bytes per [128][QPAD] tile
#define SIM_SMEM (3 * SIM_TILE)                   // q + 2 key buffers

// update one lane-private top list (NCAND slots) with value u / index idx
#define TK_UPDATE(tv, ti, mn, u, idx) do {                                   \
    if ((u) > (mn)) {                                                        \
        bool _d = false;                                                     \
        _Pragma("unroll")                                                    \
        for (int _s = 0; _s < NCAND; _s++)                                   \
            if (!_d && (tv)[_s] == (mn)) { (tv)[_s] = (u); (ti)[_s] = (idx); _d = true; } \
        (mn) = (tv)[0];                                                      \
        _Pragma("unroll")                                                    \
        for (int _s = 1; _s < NCAND; _s++) (mn) = min((mn), (tv)[_s]);       \
    }                                                                        \
} while (0)

__global__ __launch_bounds__(256, 1)
void sim_topk_bf16(const __nv_bfloat16* __restrict__ qb,
                   const __nv_bfloat16* __restrict__ kb,
                   int* __restrict__ cand) {
    extern __shared__ char smraw[];
    unsigned sbase = (unsigned)__cvta_generic_to_shared(smraw);
    __nv_bfloat16* qs  = (__nv_bfloat16*)smraw;   // [128][QPAD]
    __nv_bfloat16* ks0 = qs + 128 * QPAD;
    __nv_bfloat16* ks1 = ks0 + 128 * QPAD;

    int tid = threadIdx.x, lane = tid & 31, warp = tid >> 5;
    int row0 = blockIdx.x * 128;
    int qr = lane >> 2, kc = (lane & 3) * 2;

    // stage q panel + key chunk 0
    {
        unsigned qdst = sbase;
#pragma unroll
        for (int t = 0; t < 16; t++) {
            int g = tid + t * 256;                // 4096 uint4 per tile
            int r = g >> 5, u = (g & 31) * 8;
            cp16(qdst + (unsigned)(r * QPAD + u) * 2, qb + (size_t)(row0 + r) * 256 + u);
            cp16(qdst + SIM_TILE + (unsigned)(r * QPAD + u) * 2, kb + (size_t)r * 256 + u);
        }
        CP_COMMIT();
    }

    unsigned tvA[NCAND], tvB[NCAND]; int tiA[NCAND], tiB[NCAND];
#pragma unroll
    for (int s = 0; s < NCAND; s++) { tvA[s] = 0u; tvB[s] = 0u; tiA[s] = 0; tiB[s] = 0; }
    unsigned mnA = 0u, mnB = 0u;

    for (int ch = 0; ch < 32; ch++) {
        CP_WAIT0();
        __syncthreads();          // buffer(ch) ready; prior compute done before restage
        if (ch + 1 < 32) {        // stage next chunk into the other buffer
            unsigned dst = sbase + SIM_TILE + ((ch + 1) & 1) * SIM_TILE;
            const __nv_bfloat16* src = kb + (size_t)((ch + 1) * 128) * 256;
#pragma unroll
            for (int t = 0; t < 16; t++) {
                int g = tid + t * 256;
                int r = g >> 5, u = (g & 31) * 8;
                cp16(dst + (unsigned)(r * QPAD + u) * 2, src + (size_t)r * 256 + u);
            }
            CP_COMMIT();
        }

        const __nv_bfloat16* kbuf = (ch & 1) ? ks1 : ks0;
        float acc[16][4];
#pragma unroll
        for (int nt = 0; nt < 16; nt++)
#pragma unroll
            for (int x = 0; x < 4; x++) acc[nt][x] = 0.f;

#pragma unroll
        for (int ksp = 0; ksp < 16; ksp++) {
            int k0 = ksp * 16;
            const __nv_bfloat16* pa = qs + (warp * 16 + qr) * QPAD + k0 + kc;
            unsigned a0 = *(const unsigned*)(pa);
            unsigned a1 = *(const unsigned*)(pa + 8 * QPAD);
            unsigned a2 = *(const unsigned*)(pa + 8);
            unsigned a3 = *(const unsigned*)(pa + 8 * QPAD + 8);
#pragma unroll
            for (int nt = 0; nt < 16; nt++) {
                const __nv_bfloat16* pb = kbuf + (nt * 8 + qr) * QPAD + k0 + kc;
                unsigned B0 = *(const unsigned*)(pb);
                unsigned B1 = *(const unsigned*)(pb + 8);
                asm volatile(
                    "mma.sync.aligned.m16n8k16.row.col.f32.bf16.bf16.f32 "
                    "{%0,%1,%2,%3}, {%4,%5,%6,%7}, {%8,%9}, {%0,%1,%2,%3};\n"
                    : "+f"(acc[nt][0]), "+f"(acc[nt][1]),
                      "+f"(acc[nt][2]), "+f"(acc[nt][3])
                    : "r"(a0), "r"(a1), "r"(a2), "r"(a3), "r"(B0), "r"(B1));
            }
        }

        // fragment-direct topk update (register-only, no cross-lane ops)
        // c0,c1 -> row qr cols cb,cb+1 ; c2,c3 -> row qr+8 cols cb,cb+1
#pragma unroll
        for (int nt = 0; nt < 16; nt++) {
            int cb = ch * 128 + nt * 8 + (lane & 3) * 2;
            unsigned u;
            u = fordb(__float_as_uint(acc[nt][0])); TK_UPDATE(tvA, tiA, mnA, u, cb);
            u = fordb(__float_as_uint(acc[nt][1])); TK_UPDATE(tvA, tiA, mnA, u, cb + 1);
            u = fordb(__float_as_uint(acc[nt][2])); TK_UPDATE(tvB, tiB, mnB, u, cb);
            u = fordb(__float_as_uint(acc[nt][3])); TK_UPDATE(tvB, tiB, mnB, u, cb + 1);
        }
    }
    __syncthreads();

    // ---- exact merge: 4 lanes x top-16 -> top-16 of 64, per row ----
    unsigned* mv = (unsigned*)ks0;                // [128][64]
    int*      mi = (int*)(mv + 128 * 64);         // [128][64]
    {
        int rA = warp * 16 + qr, rB = rA + 8, sb = (lane & 3) * 16;
#pragma unroll
        for (int s = 0; s < NCAND; s++) {
            mv[rA * 64 + sb + s] = tvA[s];  mi[rA * 64 + sb + s] = tiA[s];
            mv[rB * 64 + sb + s] = tvB[s];  mi[rB * 64 + sb + s] = tiB[s];
        }
    }
    __syncthreads();
    if (tid < 128) {
        int r = tid;
#pragma unroll 1
        for (int t = 0; t < NCAND; t++) {
            unsigned best = 0; int bj = 0;
#pragma unroll 1
            for (int j = 0; j < 64; j++) {
                unsigned v = mv[r * 64 + j];
                if (v > best) { best = v; bj = j; }
            }
            mv[r * 64 + bj] = 0;
            cand[(size_t)(row0 + r) * NCAND + t] = mi[r * 64 + bj];
        }
    }
}

// ============================================================
// Exact rescore: fp32 dots for 16 candidates, exact top-8,
// softmax + weighted gather of memory_values. 1 warp per query.
// Emits retrieved as split-bf16 hi/lo.
// ============================================================
__global__ __launch_bounds__(256)
void rescore_kernel(const float* __restrict__ q, const float* __restrict__ keys,
                    const float* __restrict__ values, const int* __restrict__ cand,
                    __nv_bfloat16* __restrict__ reth, __nv_bfloat16* __restrict__ retl) {
    int lane = threadIdx.x & 31, warp = threadIdx.x >> 5;
    int g = blockIdx.x * 8 + warp;

    float qv[8];
#pragma unroll
    for (int k = 0; k < 8; k++) qv[k] = q[(size_t)g * 256 + k * 32 + lane];

    int myc = cand[(size_t)g * NCAND + (lane & 15)];
    float s[NCAND]; int kid[NCAND];
#pragma unroll
    for (int c = 0; c < NCAND; c++) {
        int ki = __shfl_sync(FULL, myc, c);
        kid[c] = ki;
        const float* kr = keys + (size_t)ki * 256;
        float d = 0.f;
#pragma unroll
        for (int k = 0; k < 8; k++) d = fmaf(qv[k], kr[k * 32 + lane], d);
#pragma unroll
        for (int o = 16; o; o >>= 1) d += __shfl_xor_sync(FULL, d, o);
        s[c] = d;
    }

    bool sel[NCAND];
    float mx = -1e30f;
#pragma unroll
    for (int c = 0; c < NCAND; c++) {
        int rk = 0;
#pragma unroll
        for (int j = 0; j < NCAND; j++)
            rk += (s[j] > s[c]) || (s[j] == s[c] && j < c);
        sel[c] = (rk < TOPK);
        if (sel[c]) mx = fmaxf(mx, s[c]);
    }
    float den = 0.f, w[NCAND];
#pragma unroll
    for (int c = 0; c < NCAND; c++) {
        w[c] = sel[c] ? __expf(s[c] - mx) : 0.f;
        den += w[c];
    }
    float inv = 1.f / den;

    float accf[8];
#pragma unroll
    for (int k = 0; k < 8; k++) accf[k] = 0.f;
#pragma unroll
    for (int c = 0; c < NCAND; c++) {
        if (sel[c]) {
            const float* vr = values + (size_t)kid[c] * 256;
            float wc = w[c] * inv;
#pragma unroll
            for (int k = 0; k < 8; k++) accf[k] = fmaf(wc, vr[k * 32 + lane], accf[k]);
        }
    }
#pragma unroll
    for (int k = 0; k < 8; k++) {
        float v = accf[k];
        __nv_bfloat16 hi = __float2bfloat16_rn(v);
        reth[(size_t)g * 256 + k * 32 + lane] = hi;
        retl[(size_t)g * 256 + k * 32 + lane] =
            __float2bfloat16_rn(v - __bfloat162float(hi));
    }
}

// ============================================================
// launch   (profiled slot = our 0-based launch index 3 -> sim)
// ============================================================
extern "C" void kernel_launch(void* const* d_in, const int* in_sizes, int n_in,
                              void* d_out, int out_size) {
    const float* query = (const float*)d_in[0];
    const float* mkeys = (const float*)d_in[1];
    const float* mvals = (const float*)d_in[2];
    const float* Wq    = (const float*)d_in[3];
    const float* bq    = (const float*)d_in[4];
    const float* W1    = (const float*)d_in[5];
    const float* b1    = (const float*)d_in[6];
    const float* W2    = (const float*)d_in[7];
    const float* b2    = (const float*)d_in[8];
    float* out = (float*)d_out;
    (void)in_sizes; (void)n_in; (void)out_size;

    float* qf;           cudaGetSymbolAddress((void**)&qf, g_q);
    __nv_bfloat16* qbf;  cudaGetSymbolAddress((void**)&qbf, g_qb);
    __nv_bfloat16* kbf;  cudaGetSymbolAddress((void**)&kbf, g_kb);
    int* candp;          cudaGetSymbolAddress((void**)&candp, g_cand);
    __nv_bfloat16 *qryh, *qryl, *reth, *retl, *hh, *hl;
    cudaGetSymbolAddress((void**)&qryh, g_qry_h);
    cudaGetSymbolAddress((void**)&qryl, g_qry_l);
    cudaGetSymbolAddress((void**)&reth, g_ret_h);
    cudaGetSymbolAddress((void**)&retl, g_ret_l);
    cudaGetSymbolAddress((void**)&hh,   g_h_h);
    cudaGetSymbolAddress((void**)&hl,   g_h_l);
    __nv_bfloat16 *wqh, *wql, *w1h, *w1l, *w2h, *w2l;
    cudaGetSymbolAddress((void**)&wqh, g_wqt_h);
    cudaGetSymbolAddress((void**)&wql, g_wqt_l);
    cudaGetSymbolAddress((void**)&w1h, g_w1t_h);
    cudaGetSymbolAddress((void**)&w1l, g_w1t_l);
    cudaGetSymbolAddress((void**)&w2h, g_w2t_h);
    cudaGetSymbolAddress((void**)&w2l, g_w2t_l);

    // 0: keys->bf16 + Wq prep
    prep_kw_kernel<<<1280, 256>>>(mkeys, Wq, kbf, wqh, wql);

    // 1: query fp32 -> split bf16
    split_f32_kernel<<<(NROWS * FD / 4) / 256, 256>>>(query, qryh, qryl);

    // 2: q = query @ Wq + bq   (fp32 out + bf16-hi out)
    cudaFuncSetAttribute(bgemm2_kernel<256, 0, 0, 1>,
                         cudaFuncAttributeMaxDynamicSharedMemorySize, BG_SMEM);
    bgemm2_kernel<256, 0, 0, 1><<<dim3(NROWS / 128, 2), 256, BG_SMEM>>>(
        qryh, qryl, nullptr, nullptr, wqh, wql, bq, qf, qbf, nullptr);

    // 3: fused sim + top-16 candidates  <-- profiled slot
    cudaFuncSetAttribute(sim_topk_bf16,
                         cudaFuncAttributeMaxDynamicSharedMemorySize, SIM_SMEM);
    sim_topk_bf16<<<NROWS / 128, 256, SIM_SMEM>>>(qbf, kbf, candp);

    // 4: exact rescore + softmax + gather (-> split-bf16 retrieved)
    rescore_kernel<<<NROWS / 8, 256>>>(qf, mkeys, mvals, candp, reth, retl);

    // 5: W1/W2 prep
    prep_w12_kernel<<<768, 256>>>(W1, W2, w1h, w1l, w2h, w2l);

    // 6: h = relu(concat(query, retrieved) @ W1 + b1)  (-> split-bf16 h)
    cudaFuncSetAttribute(bgemm2_kernel<512, 1, 1, 2>,
                         cudaFuncAttributeMaxDynamicSharedMemorySize, BG_SMEM);
    bgemm2_kernel<512, 1, 1, 2><<<dim3(NROWS / 128, 2), 256, BG_SMEM>>>(
        qryh, qryl, reth, retl, w1h, w1l, b1, nullptr, hh, hl);

    // 7: out = h @ W2 + b2  (fp32)
    cudaFuncSetAttribute(bgemm2_kernel<256, 0, 0, 0>,
                         cudaFuncAttributeMaxDynamicSharedMemorySize, BG_SMEM);
    bgemm2_kernel<256, 0, 0, 0><<<dim3(NROWS / 128, 2), 256, BG_SMEM>>>(
        hh, hl, nullptr, nullptr, w2h, w2l, b2, out, nullptr, nullptr);
}

// round 14
// speedup vs baseline: 11.1566x; 11.1349x over previous
#include <cuda_runtime.h>
#include <cuda_bf16.h>
#include <cstdint>

#define FULL 0xffffffffu
#define NROWS 65536          // B*N
#define FD 256               // feature dim
#define MMEM 4096            // memory size
#define NCAND 16             // candidates kept (top-16), exact rescore picks top-8
#define TOPK 8

// -------- scratch (static __device__ — no allocations) --------
__device__ __align__(256) float         g_q[(size_t)NROWS * FD];   // fp32 q (rescore)
__device__ __align__(256) __nv_bfloat16 g_qb[(size_t)NROWS * FD];  // bf16 hi(q) for sim
__device__ __align__(256) __nv_bfloat16 g_kb[(size_t)MMEM * FD];   // bf16 keys (sim)
__device__ __align__(256) int           g_cand[(size_t)NROWS * NCAND];
__device__ __align__(256) __nv_bfloat16 g_qry_h[(size_t)NROWS * FD];
__device__ __align__(256) __nv_bfloat16 g_qry_l[(size_t)NROWS * FD];
__device__ __align__(256) __nv_bfloat16 g_ret_h[(size_t)NROWS * FD];
__device__ __align__(256) __nv_bfloat16 g_ret_l[(size_t)NROWS * FD];
__device__ __align__(256) __nv_bfloat16 g_h_h[(size_t)NROWS * FD];
__device__ __align__(256) __nv_bfloat16 g_h_l[(size_t)NROWS * FD];
// split-bf16 transposed weights: [N=256][K] k-major, hi + lo
__device__ __align__(256) __nv_bfloat16 g_wqt_h[256 * 256], g_wqt_l[256 * 256];
__device__ __align__(256) __nv_bfloat16 g_w1t_h[256 * 512], g_w1t_l[256 * 512];
__device__ __align__(256) __nv_bfloat16 g_w2t_h[256 * 256], g_w2t_l[256 * 256];

// order-preserving float->uint map (monotone; all finite floats map > 0)
__device__ __forceinline__ unsigned ford(float f) {
    unsigned u = __float_as_uint(f);
    return (u & 0x80000000u) ? ~u : (u | 0x80000000u);
}

__device__ __forceinline__ void cp16(unsigned dst, const void* src) {
    asm volatile("cp.async.cg.shared.global [%0], [%1], 16;"
                 :: "r"(dst), "l"(src) : "memory");
}
#define CP_COMMIT() asm volatile("cp.async.commit_group;" ::: "memory")
#define CP_WAIT0()  asm volatile("cp.async.wait_group 0;" ::: "memory")
#define CP_WAIT1()  asm volatile("cp.async.wait_group 1;" ::: "memory")

// ============================================================
// launch 0: keys -> bf16 [blocks 0..1023] ; Wq transpose+split [1024..1279]
// ============================================================
__global__ void prep_kw_kernel(const float* __restrict__ keys,
                               const float* __restrict__ Wq,
                               __nv_bfloat16* __restrict__ kb,
                               __nv_bfloat16* __restrict__ wth,
                               __nv_bfloat16* __restrict__ wtl) {
    int b = blockIdx.x, tid = threadIdx.x;
    if (b < 1024) {                        // keys -> bf16, float4 granularity
        size_t i = (size_t)b * 256 + tid;
        float4 v = ((const float4*)keys)[i];
        union { __nv_bfloat16 h[4]; uint2 u; } p;
        p.h[0] = __float2bfloat16_rn(v.x);
        p.h[1] = __float2bfloat16_rn(v.y);
        p.h[2] = __float2bfloat16_rn(v.z);
        p.h[3] = __float2bfloat16_rn(v.w);
        ((uint2*)kb)[i] = p.u;
    } else {                               // Wq transpose + split (K=256)
        int idx = (b - 1024) * 256 + tid;
        int n = idx >> 8, k = idx & 255;
        float v = Wq[(size_t)k * 256 + n];
        __nv_bfloat16 h = __float2bfloat16_rn(v);
        wth[(size_t)n * 256 + k] = h;
        wtl[(size_t)n * 256 + k] = __float2bfloat16_rn(v - __bfloat162float(h));
    }
}

// ============================================================
// launch 1: query fp32 -> split bf16 hi/lo
// ============================================================
__global__ void split_f32_kernel(const float* __restrict__ x,
                                 __nv_bfloat16* __restrict__ xh,
                                 __nv_bfloat16* __restrict__ xl) {
    size_t i = (size_t)blockIdx.x * blockDim.x + threadIdx.x;
    float4 v = ((const float4*)x)[i];
    union { __nv_bfloat16 h[4]; uint2 u; } ph, pl;
    float f[4] = {v.x, v.y, v.z, v.w};
#pragma unroll
    for (int j = 0; j < 4; j++) {
        ph.h[j] = __float2bfloat16_rn(f[j]);
        pl.h[j] = __float2bfloat16_rn(f[j] - __bfloat162float(ph.h[j]));
    }
    ((uint2*)xh)[i] = ph.u;
    ((uint2*)xl)[i] = pl.u;
}

// W1 (K=512, blocks 0..511) + W2 (K=256, blocks 512..767)
__global__ void prep_w12_kernel(const float* __restrict__ W1,
                                const float* __restrict__ W2,
                                __nv_bfloat16* __restrict__ w1h,
                                __nv_bfloat16* __restrict__ w1l,
                                __nv_bfloat16* __restrict__ w2h,
                                __nv_bfloat16* __restrict__ w2l) {
    int b = blockIdx.x, tid = threadIdx.x;
    if (b < 512) {
        int idx = b * 256 + tid;
        int n = idx / 512, k = idx - n * 512;
        float v = W1[(size_t)k * 256 + n];
        __nv_bfloat16 h = __float2bfloat16_rn(v);
        w1h[(size_t)n * 512 + k] = h;
        w1l[(size_t)n * 512 + k] = __float2bfloat16_rn(v - __bfloat162float(h));
    } else {
        int idx = (b - 512) * 256 + tid;
        int n = idx >> 8, k = idx & 255;
        float v = W2[(size_t)k * 256 + n];
        __nv_bfloat16 h = __float2bfloat16_rn(v);
        w2h[(size_t)n * 256 + k] = h;
        w2l[(size_t)n * 256 + k] = __float2bfloat16_rn(v - __bfloat162float(h));
    }
}

// ============================================================
// split-bf16 tensor-core GEMM (mma.sync bf16/f32), cp.async 2-stage.
// BM=128, BN=128, BK=64.  MODE 0: C fp32.  MODE 1: C fp32 + Ch bf16-hi.
// MODE 2: Ch bf16-hi + Cl bf16-lo.  CONCAT: A = [A0 | A1] along K.
// (byte-identical math to the 3621us-proven version)
// ============================================================
#define APAD 72
#define BG_STAGE (4 * 128 * APAD * 2)
#define BG_SMEM (2 * BG_STAGE)

template <int K, int CONCAT, int RELU, int MODE>
__global__ __launch_bounds__(256)
void bgemm2_kernel(const __nv_bfloat16* __restrict__ A0h,
                   const __nv_bfloat16* __restrict__ A0l,
                   const __nv_bfloat16* __restrict__ A1h,
                   const __nv_bfloat16* __restrict__ A1l,
                   const __nv_bfloat16* __restrict__ Bth,
                   const __nv_bfloat16* __restrict__ Btl,
                   const float* __restrict__ bias,
                   float* __restrict__ C,
                   __nv_bfloat16* __restrict__ Ch,
                   __nv_bfloat16* __restrict__ Cl) {
    extern __shared__ char smraw[];
    unsigned sbase = (unsigned)__cvta_generic_to_shared(smraw);
    int tid = threadIdx.x, lane = tid & 31, warp = tid >> 5;
    int row0 = blockIdx.x * 128, col0 = blockIdx.y * 128;
    const int NITER = K / 64;

    auto prefetch = [&](int it, int buf) {
        int kb = it * 64;
        const __nv_bfloat16 *Ah, *Al;
        if (CONCAT && kb >= 256) { Ah = A1h + (kb - 256); Al = A1l + (kb - 256); }
        else                     { Ah = A0h + kb;         Al = A0l + kb;         }
        const int astr = CONCAT ? 256 : K;
        unsigned s = sbase + buf * BG_STAGE;
#pragma unroll
        for (int t = 0; t < 4; t++) {
            int g = tid + t * 256;
            int r = g >> 3, q = (g & 7) * 8;
            unsigned off = (unsigned)(r * APAD + q) * 2;
            cp16(s + off,                      Ah + (size_t)(row0 + r) * astr + q);
            cp16(s + 128 * APAD * 2 + off,     Al + (size_t)(row0 + r) * astr + q);
            cp16(s + 2 * 128 * APAD * 2 + off, Bth + (size_t)(col0 + r) * K + kb + q);
            cp16(s + 3 * 128 * APAD * 2 + off, Btl + (size_t)(col0 + r) * K + kb + q);
        }
        CP_COMMIT();
    };

    int wm = warp >> 1, wn = warp & 1;
    int qr = lane >> 2, kc = (lane & 3) * 2;

    float acc[2][8][4];
#pragma unroll
    for (int mt = 0; mt < 2; mt++)
#pragma unroll
        for (int nt = 0; nt < 8; nt++)
#pragma unroll
            for (int x = 0; x < 4; x++) acc[mt][nt][x] = 0.f;

    prefetch(0, 0);

    for (int it = 0; it < NITER; it++) {
        if (it + 1 < NITER) { prefetch(it + 1, (it + 1) & 1); CP_WAIT1(); }
        else                { CP_WAIT0(); }
        __syncthreads();
        __nv_bfloat16* Ash = (__nv_bfloat16*)(smraw + (it & 1) * BG_STAGE);
        __nv_bfloat16* Asl = Ash + 128 * APAD;
        __nv_bfloat16* Bsh = Asl + 128 * APAD;
        __nv_bfloat16* Bsl = Bsh + 128 * APAD;

#pragma unroll
        for (int ksp = 0; ksp < 4; ksp++) {
            int k0 = ksp * 16;
            unsigned Ahf[2][4], Alf[2][4];
#pragma unroll
            for (int mt = 0; mt < 2; mt++) {
                const __nv_bfloat16* ph = Ash + (wm * 32 + mt * 16 + qr) * APAD + k0 + kc;
                const __nv_bfloat16* pl = Asl + (wm * 32 + mt * 16 + qr) * APAD + k0 + kc;
                Ahf[mt][0] = *(const unsigned*)(ph);
                Ahf[mt][1] = *(const unsigned*)(ph + 8 * APAD);
                Ahf[mt][2] = *(const unsigned*)(ph + 8);
                Ahf[mt][3] = *(const unsigned*)(ph + 8 * APAD + 8);
                Alf[mt][0] = *(const unsigned*)(pl);
                Alf[mt][1] = *(const unsigned*)(pl + 8 * APAD);
                Alf[mt][2] = *(const unsigned*)(pl + 8);
                Alf[mt][3] = *(const unsigned*)(pl + 8 * APAD + 8);
            }
#pragma unroll
            for (int nt = 0; nt < 8; nt++) {
                const __nv_bfloat16* pbh = Bsh + (wn * 64 + nt * 8 + qr) * APAD + k0 + kc;
                const __nv_bfloat16* pbl = Bsl + (wn * 64 + nt * 8 + qr) * APAD + k0 + kc;
                unsigned Bh0 = *(const unsigned*)(pbh);
                unsigned Bh1 = *(const unsigned*)(pbh + 8);
                unsigned Bl0 = *(const unsigned*)(pbl);
                unsigned Bl1 = *(const unsigned*)(pbl + 8);
#pragma unroll
                for (int mt = 0; mt < 2; mt++) {
#define MMA_BF16(Areg, B0, B1)                                              \
    asm volatile(                                                           \
        "mma.sync.aligned.m16n8k16.row.col.f32.bf16.bf16.f32 "              \
        "{%0,%1,%2,%3}, {%4,%5,%6,%7}, {%8,%9}, {%0,%1,%2,%3};\n"           \
        : "+f"(acc[mt][nt][0]), "+f"(acc[mt][nt][1]),                       \
          "+f"(acc[mt][nt][2]), "+f"(acc[mt][nt][3])                        \
        : "r"(Areg[mt][0]), "r"(Areg[mt][1]), "r"(Areg[mt][2]),             \
          "r"(Areg[mt][3]), "r"(B0), "r"(B1))
                    MMA_BF16(Ahf, Bh0, Bh1);   // hi*hi
                    MMA_BF16(Ahf, Bl0, Bl1);   // hi*lo
                    MMA_BF16(Alf, Bh0, Bh1);   // lo*hi
#undef MMA_BF16
                }
            }
        }
        __syncthreads();
    }

    // epilogue
#pragma unroll
    for (int mt = 0; mt < 2; mt++) {
        int rA = row0 + wm * 32 + mt * 16 + qr;
#pragma unroll
        for (int nt = 0; nt < 8; nt++) {
            int c = col0 + wn * 64 + nt * 8 + (lane & 3) * 2;
            float b0 = bias[c], b1 = bias[c + 1];
            float v0 = acc[mt][nt][0] + b0, v1 = acc[mt][nt][1] + b1;
            float v2 = acc[mt][nt][2] + b0, v3 = acc[mt][nt][3] + b1;
            if (RELU) {
                v0 = fmaxf(v0, 0.f); v1 = fmaxf(v1, 0.f);
                v2 = fmaxf(v2, 0.f); v3 = fmaxf(v3, 0.f);
            }
            if (MODE == 0 || MODE == 1) {
                *(float2*)(C + (size_t)rA * 256 + c)       = make_float2(v0, v1);
                *(float2*)(C + (size_t)(rA + 8) * 256 + c) = make_float2(v2, v3);
            }
            if (MODE == 1) {   // bf16-hi copy for the sim kernel
                union { __nv_bfloat16 h[2]; unsigned u; } p;
                p.h[0] = __float2bfloat16_rn(v0); p.h[1] = __float2bfloat16_rn(v1);
                *(unsigned*)(Ch + (size_t)rA * 256 + c) = p.u;
                p.h[0] = __float2bfloat16_rn(v2); p.h[1] = __float2bfloat16_rn(v3);
                *(unsigned*)(Ch + (size_t)(rA + 8) * 256 + c) = p.u;
            }
            if (MODE == 2) {   // split-bf16 hi/lo
                union { __nv_bfloat16 h[2]; unsigned u; } p, q;
                p.h[0] = __float2bfloat16_rn(v0);
                p.h[1] = __float2bfloat16_rn(v1);
                q.h[0] = __float2bfloat16_rn(v0 - __bfloat162float(p.h[0]));
                q.h[1] = __float2bfloat16_rn(v1 - __bfloat162float(p.h[1]));
                *(unsigned*)(Ch + (size_t)rA * 256 + c) = p.u;
                *(unsigned*)(Cl + (size_t)rA * 256 + c) = q.u;
                p.h[0] = __float2bfloat16_rn(v2);
                p.h[1] = __float2bfloat16_rn(v3);
                q.h[0] = __float2bfloat16_rn(v2 - __bfloat162float(p.h[0]));
                q.h[1] = __float2bfloat16_rn(v3 - __bfloat162float(p.h[1]));
                *(unsigned*)(Ch + (size_t)(rA + 8) * 256 + c) = p.u;
                *(unsigned*)(Cl + (size_t)(rA + 8) * 256 + c) = q.u;
            }
        }
    }
}

// ============================================================
// Fused sim GEMM (bf16 mma.sync) + parallel streaming top-16.
// *** R7-PROVEN DESIGN (3621us run), verbatim except cp.async staging ***
// 128-query tile per CTA, 32 chunks of 128 keys, K=256.
// Topk: unsorted 16-slot smem buffer per row; min via redux.sync.min.u32
// on order-mapped floats; 2 rows per warp concurrently (16-lane halves).
// ============================================================
#define QPAD 264   // 256 + 8 bf16 pad (conflict-free fragment LDS)
#define SPAD 144   // sim row stride in floats
#define SIM_SMEM (128*QPAD*2 /*q*/ + 128*QPAD*2 /*keys*/ + 128*SPAD*4 /*sim*/ \
                  + 128*NCAND*4 /*tvu*/ + 128*NCAND*4 /*ti*/)

__global__ __launch_bounds__(256, 1)
void sim_topk_kernel(const __nv_bfloat16* __restrict__ qb,
                     const __nv_bfloat16* __restrict__ kb,
                     int* __restrict__ cand) {
    extern __shared__ char smraw[];
    unsigned sbase = (unsigned)__cvta_generic_to_shared(smraw);
    __nv_bfloat16* qs = (__nv_bfloat16*)smraw;            // [128][QPAD]
    __nv_bfloat16* ks = qs + 128 * QPAD;                  // [128][QPAD]
    float*    sim = (float*)(ks + 128 * QPAD);            // [128][SPAD]
    unsigned* tvu = (unsigned*)(sim + 128 * SPAD);        // [128][16] slot vals
    int*      ti  = (int*)(tvu + 128 * NCAND);            // [128][16] slot idxs

    int tid = threadIdx.x, lane = tid & 31, warp = tid >> 5;
    int row0 = blockIdx.x * 128;
    const unsigned KSB = sbase + 128 * QPAD * 2;          // smem addr of ks

    // load q tile (cp.async; bf16 hi, already converted)
#pragma unroll
    for (int t = 0; t < 16; t++) {
        int g = tid + t * 256;                            // 4096 uint4
        int r = g >> 5, u = (g & 31) * 8;
        cp16(sbase + (unsigned)(r * QPAD + u) * 2, qb + (size_t)(row0 + r) * 256 + u);
    }
    CP_COMMIT(); CP_WAIT0();
    __syncthreads();

    int wm = warp >> 1, wn = warp & 1;
    int qr = lane >> 2, kc = (lane & 3) * 2;
    int half = lane >> 4, sl = lane & 15;
    unsigned hm = half ? 0xFFFF0000u : 0x0000FFFFu;

    for (int ch = 0; ch < 32; ch++) {
        // stream keys chunk into smem (cp.async, single buffer — same
        // barrier structure as the proven LDG+STS version)
#pragma unroll
        for (int t = 0; t < 16; t++) {
            int g = tid + t * 256;
            int r = g >> 5, u = (g & 31) * 8;
            cp16(KSB + (unsigned)(r * QPAD + u) * 2,
                 kb + (size_t)(ch * 128 + r) * 256 + u);
        }
        CP_COMMIT(); CP_WAIT0();
        __syncthreads();

        float acc[2][8][4];
#pragma unroll
        for (int mt = 0; mt < 2; mt++)
#pragma unroll
            for (int nt = 0; nt < 8; nt++)
#pragma unroll
                for (int x = 0; x < 4; x++) acc[mt][nt][x] = 0.f;

#pragma unroll
        for (int ksp = 0; ksp < 16; ksp++) {
            int k0 = ksp * 16;
            unsigned A[2][4];
#pragma unroll
            for (int mt = 0; mt < 2; mt++) {
                const __nv_bfloat16* p0 = qs + (wm * 32 + mt * 16 + qr) * QPAD + k0 + kc;
                A[mt][0] = *(const unsigned*)(p0);
                A[mt][1] = *(const unsigned*)(p0 + 8 * QPAD);
                A[mt][2] = *(const unsigned*)(p0 + 8);
                A[mt][3] = *(const unsigned*)(p0 + 8 * QPAD + 8);
            }
#pragma unroll
            for (int nt = 0; nt < 8; nt++) {
                const __nv_bfloat16* pb = ks + (wn * 64 + nt * 8 + qr) * QPAD + k0 + kc;
                unsigned B0 = *(const unsigned*)(pb);
                unsigned B1 = *(const unsigned*)(pb + 8);
#pragma unroll
                for (int mt = 0; mt < 2; mt++) {
                    asm volatile(
                        "mma.sync.aligned.m16n8k16.row.col.f32.bf16.bf16.f32 "
                        "{%0,%1,%2,%3}, {%4,%5,%6,%7}, {%8,%9}, {%0,%1,%2,%3};\n"
                        : "+f"(acc[mt][nt][0]), "+f"(acc[mt][nt][1]),
                          "+f"(acc[mt][nt][2]), "+f"(acc[mt][nt][3])
                        : "r"(A[mt][0]), "r"(A[mt][1]), "r"(A[mt][2]), "r"(A[mt][3]),
                          "r"(B0), "r"(B1));
                }
            }
        }

        // stage sim tile to smem
#pragma unroll
        for (int mt = 0; mt < 2; mt++)
#pragma unroll
            for (int nt = 0; nt < 8; nt++) {
                int r = wm * 32 + mt * 16 + qr;
                int c = wn * 64 + nt * 8 + (lane & 3) * 2;
                *(float2*)&sim[r * SPAD + c] = make_float2(acc[mt][nt][0], acc[mt][nt][1]);
                *(float2*)&sim[(r + 8) * SPAD + c] = make_float2(acc[mt][nt][2], acc[mt][nt][3]);
            }
        __syncthreads();

        // ---- parallel top-16: warp handles rows warp*16..+15 as 8 pairs ----
#pragma unroll 1
        for (int p = 0; p < 8; p++) {
            int r = warp * 16 + 2 * p + half;
            unsigned su; int sidx;
            if (ch == 0) { su = 0u; sidx = 0; }
            else { su = tvu[r * 16 + sl]; sidx = ti[r * 16 + sl]; }
            unsigned mn = __reduce_min_sync(hm, su);
            const float* simr = sim + r * SPAD;
#pragma unroll 1
            for (int j = 0; j < 8; j++) {
                unsigned up = ford(simr[j * 16 + sl]);
                unsigned bal = __ballot_sync(hm, up > mn);
                unsigned hbal = (half ? (bal >> 16) : bal) & 0xFFFFu;
                while (hbal) {
                    int s = __ffs(hbal) - 1; hbal &= hbal - 1;
                    unsigned cu = __shfl_sync(hm, up, (half << 4) + s);
                    if (cu > mn) {
                        unsigned mb = __ballot_sync(hm, su == mn);
                        int ms = __ffs(half ? (mb >> 16) : mb) - 1;
                        if (sl == ms) { su = cu; sidx = ch * 128 + j * 16 + s; }
                        mn = __reduce_min_sync(hm, su);
                    }
                }
            }
            tvu[r * 16 + sl] = su;
            ti[r * 16 + sl] = sidx;
        }
        __syncthreads();
    }

    for (int rr = 0; rr < 16; rr++) {
        int r = warp * 16 + rr;
        if (lane < NCAND) cand[(size_t)(row0 + r) * NCAND + lane] = ti[r * 16 + lane];
    }
}

// ============================================================
// Exact rescore: fp32 dots for 16 candidates, exact top-8,
// softmax + weighted gather of memory_values. 1 warp per query.
// Emits retrieved as split-bf16 hi/lo.
// ============================================================
__global__ __launch_bounds__(256)
void rescore_kernel(const float* __restrict__ q, const float* __restrict__ keys,
                    const float* __restrict__ values, const int* __restrict__ cand,
                    __nv_bfloat16* __restrict__ reth, __nv_bfloat16* __restrict__ retl) {
    int lane = threadIdx.x & 31, warp = threadIdx.x >> 5;
    int g = blockIdx.x * 8 + warp;

    float qv[8];
#pragma unroll
    for (int k = 0; k < 8; k++) qv[k] = q[(size_t)g * 256 + k * 32 + lane];

    int myc = cand[(size_t)g * NCAND + (lane & 15)];
    float s[NCAND]; int kid[NCAND];
#pragma unroll
    for (int c = 0; c < NCAND; c++) {
        int ki = __shfl_sync(FULL, myc, c);
        kid[c] = ki;
        const float* kr = keys + (size_t)ki * 256;
        float d = 0.f;
#pragma unroll
        for (int k = 0; k < 8; k++) d = fmaf(qv[k], kr[k * 32 + lane], d);
#pragma unroll
        for (int o = 16; o; o >>= 1) d += __shfl_xor_sync(FULL, d, o);
        s[c] = d;
    }

    bool sel[NCAND];
    float mx = -1e30f;
#pragma unroll
    for (int c = 0; c < NCAND; c++) {
        int rk = 0;
#pragma unroll
        for (int j = 0; j < NCAND; j++)
            rk += (s[j] > s[c]) || (s[j] == s[c] && j < c);
        sel[c] = (rk < TOPK);
        if (sel[c]) mx = fmaxf(mx, s[c]);
    }
    float den = 0.f, w[NCAND];
#pragma unroll
    for (int c = 0; c < NCAND; c++) {
        w[c] = sel[c] ? __expf(s[c] - mx) : 0.f;
        den += w[c];
    }
    float inv = 1.f / den;

    float accf[8];
#pragma unroll
    for (int k = 0; k < 8; k++) accf[k] = 0.f;
#pragma unroll
    for (int c = 0; c < NCAND; c++) {
        if (sel[c]) {
            const float* vr = values + (size_t)kid[c] * 256;
            float wc = w[c] * inv;
#pragma unroll
            for (int k = 0; k < 8; k++) accf[k] = fmaf(wc, vr[k * 32 + lane], accf[k]);
        }
    }
#pragma unroll
    for (int k = 0; k < 8; k++) {
        float v = accf[k];
        __nv_bfloat16 hi = __float2bfloat16_rn(v);
        reth[(size_t)g * 256 + k * 32 + lane] = hi;
        retl[(size_t)g * 256 + k * 32 + lane] =
            __float2bfloat16_rn(v - __bfloat162float(hi));
    }
}

// ============================================================
// launch   (profiled slot = our 0-based launch index 3 -> sim)
// ============================================================
extern "C" void kernel_launch(void* const* d_in, const int* in_sizes, int n_in,
                              void* d_out, int out_size) {
    const float* query = (const float*)d_in[0];
    const float* mkeys = (const float*)d_in[1];
    const float* mvals = (const float*)d_in[2];
    const float* Wq    = (const float*)d_in[3];
    const float* bq    = (const float*)d_in[4];
    const float* W1    = (const float*)d_in[5];
    const float* b1    = (const float*)d_in[6];
    const float* W2    = (const float*)d_in[7];
    const float* b2    = (const float*)d_in[8];
    float* out = (float*)d_out;
    (void)in_sizes; (void)n_in; (void)out_size;

    float* qf;           cudaGetSymbolAddress((void**)&qf, g_q);
    __nv_bfloat16* qbf;  cudaGetSymbolAddress((void**)&qbf, g_qb);
    __nv_bfloat16* kbf;  cudaGetSymbolAddress((void**)&kbf, g_kb);
    int* candp;          cudaGetSymbolAddress((void**)&candp, g_cand);
    __nv_bfloat16 *qryh, *qryl, *reth, *retl, *hh, *hl;
    cudaGetSymbolAddress((void**)&qryh, g_qry_h);
    cudaGetSymbolAddress((void**)&qryl, g_qry_l);
    cudaGetSymbolAddress((void**)&reth, g_ret_h);
    cudaGetSymbolAddress((void**)&retl, g_ret_l);
    cudaGetSymbolAddress((void**)&hh,   g_h_h);
    cudaGetSymbolAddress((void**)&hl,   g_h_l);
    __nv_bfloat16 *wqh, *wql, *w1h, *w1l, *w2h, *w2l;
    cudaGetSymbolAddress((void**)&wqh, g_wqt_h);
    cudaGetSymbolAddress((void**)&wql, g_wqt_l);
    cudaGetSymbolAddress((void**)&w1h, g_w1t_h);
    cudaGetSymbolAddress((void**)&w1l, g_w1t_l);
    cudaGetSymbolAddress((void**)&w2h, g_w2t_h);
    cudaGetSymbolAddress((void**)&w2l, g_w2t_l);

    // 0: keys->bf16 + Wq prep
    prep_kw_kernel<<<1280, 256>>>(mkeys, Wq, kbf, wqh, wql);

    // 1: query fp32 -> split bf16
    split_f32_kernel<<<(NROWS * FD / 4) / 256, 256>>>(query, qryh, qryl);

    // 2: q = query @ Wq + bq   (fp32 out + bf16-hi out)
    cudaFuncSetAttribute(bgemm2_kernel<256, 0, 0, 1>,
                         cudaFuncAttributeMaxDynamicSharedMemorySize, BG_SMEM);
    bgemm2_kernel<256, 0, 0, 1><<<dim3(NROWS / 128, 2), 256, BG_SMEM>>>(
        qryh, qryl, nullptr, nullptr, wqh, wql, bq, qf, qbf, nullptr);

    // 3: fused sim + top-16 candidates  <-- profiled slot
    cudaFuncSetAttribute(sim_topk_kernel,
                         cudaFuncAttributeMaxDynamicSharedMemorySize, SIM_SMEM);
    sim_topk_kernel<<<NROWS / 128, 256, SIM_SMEM>>>(qbf, kbf, candp);

    // 4: exact rescore + softmax + gather (-> split-bf16 retrieved)
    rescore_kernel<<<NROWS / 8, 256>>>(qf, mkeys, mvals, candp, reth, retl);

    // 5: W1/W2 prep
    prep_w12_kernel<<<768, 256>>>(W1, W2, w1h, w1l, w2h, w2l);

    // 6: h = relu(concat(query, retrieved) @ W1 + b1)  (-> split-bf16 h)
    cudaFuncSetAttribute(bgemm2_kernel<512, 1, 1, 2>,
                         cudaFuncAttributeMaxDynamicSharedMemorySize, BG_SMEM);
    bgemm2_kernel<512, 1, 1, 2><<<dim3(NROWS / 128, 2), 256, BG_SMEM>>>(
        qryh, qryl, reth, retl, w1h, w1l, b1, nullptr, hh, hl);

    // 7: out = h @ W2 + b2  (fp32)
    cudaFuncSetAttribute(bgemm2_kernel<256, 0, 0, 0>,
                         cudaFuncAttributeMaxDynamicSharedMemorySize, BG_SMEM);
    bgemm2_kernel<256, 0, 0, 0><<<dim3(NROWS / 128, 2), 256, BG_SMEM>>>(
        hh, hl, nullptr, nullptr, w2h, w2l, b2, out, nullptr, nullptr);
}